// round 1
// baseline (speedup 1.0000x reference)
#include <cuda_runtime.h>
#include <math.h>
#include <stdint.h>

#define N_NODES 50000
#define N_EDGES 800000
#define D 128

// ---- scratch (static __device__ arrays; no allocation) ----
__device__ float    g_z[(size_t)N_NODES * D];     // fc output (reused both layers)
__device__ float    g_h1[(size_t)N_NODES * D];    // layer-1 aggregation / h1
__device__ float    g_e[N_EDGES];                 // per-edge e, then ex
__device__ float    g_ssrc[N_NODES];
__device__ float    g_sdst[N_NODES];
__device__ unsigned g_mkey[N_NODES];              // order-encoded float max
__device__ float    g_denom[N_NODES];

// ---- helpers ----
__device__ __forceinline__ unsigned fenc(float f) {
    unsigned u = __float_as_uint(f);
    return (u & 0x80000000u) ? ~u : (u | 0x80000000u);
}
__device__ __forceinline__ float fdec(unsigned u) {
    return __uint_as_float((u & 0x80000000u) ? (u & 0x7FFFFFFFu) : ~u);
}

__device__ __forceinline__ void red_add_v4(float* addr, float4 v) {
    asm volatile("red.global.add.v4.f32 [%0], {%1, %2, %3, %4};"
                 :: "l"(addr), "f"(v.x), "f"(v.y), "f"(v.z), "f"(v.w)
                 : "memory");
}

// ---- GEMM: C[M,128] = A[M,K] @ W[128,K]^T + bias ----
// BM=64, BN=128, BK=32, 256 threads, per-thread 8x4 microtile.
__global__ __launch_bounds__(256) void gemm_bias(
    const float* __restrict__ A, const float* __restrict__ W,
    const float* __restrict__ bias, float* __restrict__ C,
    int M, int K)
{
    __shared__ __align__(16) float As[32][68];   // [k][m], padded
    __shared__ __align__(16) float Bs[32][132];  // [k][n], padded

    const int tid = threadIdx.x;
    const int tx = tid & 31;        // n-groups of 4 -> covers 128
    const int ty = tid >> 5;        // m-groups of 8 -> covers 64
    const int m0 = blockIdx.x * 64;

    float acc[8][4];
#pragma unroll
    for (int i = 0; i < 8; i++)
#pragma unroll
        for (int j = 0; j < 4; j++) acc[i][j] = 0.f;

    for (int k0 = 0; k0 < K; k0 += 32) {
        // A tile: 64x32 floats = 512 float4, 2 per thread
#pragma unroll
        for (int l = 0; l < 2; l++) {
            int idx = tid + l * 256;
            int row = idx >> 3;
            int kc  = (idx & 7) << 2;
            float4 v = make_float4(0.f, 0.f, 0.f, 0.f);
            if (m0 + row < M)
                v = *(const float4*)(A + (size_t)(m0 + row) * K + k0 + kc);
            As[kc + 0][row] = v.x; As[kc + 1][row] = v.y;
            As[kc + 2][row] = v.z; As[kc + 3][row] = v.w;
        }
        // W tile: 128x32 floats = 1024 float4, 4 per thread
#pragma unroll
        for (int l = 0; l < 4; l++) {
            int idx = tid + l * 256;
            int n  = idx >> 3;
            int kc = (idx & 7) << 2;
            float4 v = *(const float4*)(W + (size_t)n * K + k0 + kc);
            Bs[kc + 0][n] = v.x; Bs[kc + 1][n] = v.y;
            Bs[kc + 2][n] = v.z; Bs[kc + 3][n] = v.w;
        }
        __syncthreads();

#pragma unroll
        for (int k = 0; k < 32; k++) {
            float4 a0 = *(const float4*)&As[k][ty * 8];
            float4 a1 = *(const float4*)&As[k][ty * 8 + 4];
            float4 bb = *(const float4*)&Bs[k][tx * 4];
            float a[8] = {a0.x, a0.y, a0.z, a0.w, a1.x, a1.y, a1.z, a1.w};
            float b[4] = {bb.x, bb.y, bb.z, bb.w};
#pragma unroll
            for (int i = 0; i < 8; i++)
#pragma unroll
                for (int j = 0; j < 4; j++)
                    acc[i][j] = fmaf(a[i], b[j], acc[i][j]);
        }
        __syncthreads();
    }

    float4 bv = *(const float4*)(bias + tx * 4);
#pragma unroll
    for (int i = 0; i < 8; i++) {
        int m = m0 + ty * 8 + i;
        if (m < M) {
            float4 o;
            o.x = acc[i][0] + bv.x; o.y = acc[i][1] + bv.y;
            o.z = acc[i][2] + bv.z; o.w = acc[i][3] + bv.w;
            *(float4*)(C + (size_t)m * D + tx * 4) = o;
        }
    }
}

// ---- per-node attention scalars: ssrc = z.a[:128], sdst = z.a[128:] ----
__global__ __launch_bounds__(256) void node_scalars(
    const float* __restrict__ z, const float* __restrict__ a,
    float* __restrict__ ssrc, float* __restrict__ sdst)
{
    int warp = (blockIdx.x * blockDim.x + threadIdx.x) >> 5;
    int lane = threadIdx.x & 31;
    if (warp >= N_NODES) return;
    float4 zv = *(const float4*)(z + (size_t)warp * D + lane * 4);
    float4 as = *(const float4*)(a + lane * 4);
    float4 ad = *(const float4*)(a + D + lane * 4);
    float s1 = zv.x * as.x + zv.y * as.y + zv.z * as.z + zv.w * as.w;
    float s2 = zv.x * ad.x + zv.y * ad.y + zv.z * ad.z + zv.w * ad.w;
#pragma unroll
    for (int o = 16; o; o >>= 1) {
        s1 += __shfl_xor_sync(0xFFFFFFFFu, s1, o);
        s2 += __shfl_xor_sync(0xFFFFFFFFu, s2, o);
    }
    if (lane == 0) { ssrc[warp] = s1; sdst[warp] = s2; }
}

// ---- init per-layer state: agg=0, mkey=enc(-inf), denom=0 ----
__global__ __launch_bounds__(256) void init_layer(float* __restrict__ agg)
{
    int i = blockIdx.x * blockDim.x + threadIdx.x;
    if (i < N_NODES * D) agg[i] = 0.f;
    if (i < N_NODES) { g_mkey[i] = 0x007FFFFFu; g_denom[i] = 0.f; }
}

// ---- edge pass A: e = leaky(ssrc[src] + sdst[dst] + ab); segment max ----
__global__ __launch_bounds__(256) void edge_pass_a(
    const int* __restrict__ src, const int* __restrict__ dst,
    const float* __restrict__ ab)
{
    int i = blockIdx.x * blockDim.x + threadIdx.x;
    if (i >= N_EDGES) return;
    int s = src[i], d = dst[i];
    float e = g_ssrc[s] + g_sdst[d] + ab[0];
    e = (e > 0.f) ? e : 0.01f * e;
    g_e[i] = e;
    atomicMax(&g_mkey[d], fenc(e));
}

// ---- edge pass B: ex = exp(e - m[dst]); segment sum ----
__global__ __launch_bounds__(256) void edge_pass_b(const int* __restrict__ dst)
{
    int i = blockIdx.x * blockDim.x + threadIdx.x;
    if (i >= N_EDGES) return;
    int d = dst[i];
    float m = fdec(g_mkey[d]);
    float ex = expf(g_e[i] - m);
    g_e[i] = ex;
    atomicAdd(&g_denom[d], ex);
}

// ---- edge pass C: agg[dst] += (ex/denom[dst]) * z[src]  (warp per edge) ----
__global__ __launch_bounds__(256) void edge_pass_c(
    const int* __restrict__ src, const int* __restrict__ dst,
    const float* __restrict__ z, float* __restrict__ agg)
{
    int warp = (blockIdx.x * blockDim.x + threadIdx.x) >> 5;
    int lane = threadIdx.x & 31;
    if (warp >= N_EDGES) return;
    int s = src[warp], d = dst[warp];
    float alpha = g_e[warp] / g_denom[d];
    float4 zv = *(const float4*)(z + (size_t)s * D + lane * 4);
    zv.x *= alpha; zv.y *= alpha; zv.z *= alpha; zv.w *= alpha;
    red_add_v4(agg + (size_t)d * D + lane * 4, zv);
}

// ---- ELU in place ----
__global__ __launch_bounds__(256) void elu_inplace(float* __restrict__ x, int n)
{
    int i = blockIdx.x * blockDim.x + threadIdx.x;
    if (i >= n) return;
    float v = x[i];
    x[i] = (v > 0.f) ? v : expm1f(v);
}

extern "C" void kernel_launch(void* const* d_in, const int* in_sizes, int n_in,
                              void* d_out, int out_size)
{
    const float* h   = (const float*)d_in[0];
    const int*   src = (const int*)  d_in[1];
    const int*   dst = (const int*)  d_in[2];
    const float* W1  = (const float*)d_in[3];
    const float* b1  = (const float*)d_in[4];
    const float* a1  = (const float*)d_in[5];
    const float* ab1 = (const float*)d_in[6];
    const float* W2  = (const float*)d_in[7];
    const float* b2  = (const float*)d_in[8];
    const float* a2  = (const float*)d_in[9];
    const float* ab2 = (const float*)d_in[10];
    float* out = (float*)d_out;

    float *z, *h1, *ssrc, *sdst;
    cudaGetSymbolAddress((void**)&z,    g_z);
    cudaGetSymbolAddress((void**)&h1,   g_h1);
    cudaGetSymbolAddress((void**)&ssrc, g_ssrc);
    cudaGetSymbolAddress((void**)&sdst, g_sdst);

    const int GEMM_BLOCKS = (N_NODES + 63) / 64;      // 782
    const int NODE_ELEMS  = N_NODES * D;              // 6.4M
    const int ELEM_BLOCKS = (NODE_ELEMS + 255) / 256; // 25000
    const int SCAL_BLOCKS = (N_NODES + 7) / 8;        // 6250 (8 warps/blk)
    const int EDGE_BLOCKS = (N_EDGES + 255) / 256;    // 3125
    const int EDGEW_BLOCKS = (N_EDGES + 7) / 8;       // 100000 (8 warps/blk)

    // ---- layer 1 ----
    gemm_bias<<<GEMM_BLOCKS, 256>>>(h, W1, b1, z, N_NODES, 256);
    node_scalars<<<SCAL_BLOCKS, 256>>>(z, a1, ssrc, sdst);
    init_layer<<<ELEM_BLOCKS, 256>>>(h1);
    edge_pass_a<<<EDGE_BLOCKS, 256>>>(src, dst, ab1);
    edge_pass_b<<<EDGE_BLOCKS, 256>>>(dst);
    edge_pass_c<<<EDGEW_BLOCKS, 256>>>(src, dst, z, h1);
    elu_inplace<<<ELEM_BLOCKS, 256>>>(h1, NODE_ELEMS);

    // ---- layer 2 ----
    gemm_bias<<<GEMM_BLOCKS, 256>>>(h1, W2, b2, z, N_NODES, 128);
    node_scalars<<<SCAL_BLOCKS, 256>>>(z, a2, ssrc, sdst);
    init_layer<<<ELEM_BLOCKS, 256>>>(out);
    edge_pass_a<<<EDGE_BLOCKS, 256>>>(src, dst, ab2);
    edge_pass_b<<<EDGE_BLOCKS, 256>>>(dst);
    edge_pass_c<<<EDGEW_BLOCKS, 256>>>(src, dst, z, out);
    elu_inplace<<<ELEM_BLOCKS, 256>>>(out, NODE_ELEMS);
}